// round 14
// baseline (speedup 1.0000x reference)
#include <cuda_runtime.h>
#include <cuda_fp16.h>
#include <cstdint>

// N=2048, F_IN=128, F_OUT=64
//   H = X@W + b
//   out[j,f] = sum_k mf[j,k]*H[k,f]* (sum_i A[j,i]*H[i,f]*mh[i,k])
// Per f: G_f = A . diag(h_f) . mh  (fp16 mma.sync, fp32 accum), k contracted
// immediately in the epilogue. mh pre-transposed fp16 [k][i]; B frags via
// ldmatrix.x4; H folded via HMUL2 (packed-H: 2x LDS128 per ks).
// R14 = R13 with:
//  (a) warp layout 4j x 2k (mt=2, nt=4): halves the 4x-redundant A-ldmatrix
//      stream (ldm4 40->32/warp/chunk, smem wavefronts -20%), pays +128 HMUL2
//      (ALU slack);
//  (b) zero_out folded into prep_H -> 4 launches, so the ncu capture slot
//      lands on interaction_main.

#define NN   2048
#define FIN  128
#define FOUT 64

#define JT 128
#define KT 64
#define FB 4
#define IC 128
#define CPT 16            // chunks per tile
#define NTILES 8192       // 16 jt * 32 kt * 16 fq

// ---- smem: 4 ring stages {A, mhT, Hp} + parity Hk ----
#define ST_A   0          // [128 j][128 i] fp16, 256B rows, XOR16 swz = 32768
#define ST_MH  32768      // [64 k][128 i] fp16                       = 16384
#define ST_H   49152      // [64 ipair][4 f] half2 (16B/ipair)        = 1024
#define STAGE  50176
#define NSTG   4
#define SM_HK  (NSTG * STAGE)          // 200704; 2 x [64][4] fp32 = 2048
#define SMEM_TOTAL (SM_HK + 2048)      // 202752

__device__ float  g_H[NN * FOUT];          // fp32 H for epilogue
__device__ __half g_Hp[16 * 1024 * 8];     // packed [fq][ipair][f][2] fp16
__device__ __half g_Ah[(size_t)NN * NN];   // adjacency fp16 [j][i]
__device__ __half g_mhT[(size_t)NN * NN];  // mask_hadamard fp16 transposed [k][i]

// ---------------- helpers ----------------
__device__ __forceinline__ uint32_t smem_to_u32(const void* p) {
    uint32_t a;
    asm("{ .reg .u64 t; cvta.to.shared.u64 t, %1; cvt.u32.u64 %0, t; }"
        : "=r"(a) : "l"(p));
    return a;
}
__device__ __forceinline__ void cp16(uint32_t dst, const void* src) {
    asm volatile("cp.async.cg.shared.global [%0], [%1], 16;" :: "r"(dst), "l"(src));
}
__device__ __forceinline__ void cp_commit() {
    asm volatile("cp.async.commit_group;" ::: "memory");
}
__device__ __forceinline__ uint4 lds128(uint32_t addr) {
    uint4 v;
    asm volatile("ld.shared.v4.b32 {%0,%1,%2,%3}, [%4];"
                 : "=r"(v.x), "=r"(v.y), "=r"(v.z), "=r"(v.w) : "r"(addr));
    return v;
}
__device__ __forceinline__ void ldm4(uint32_t* r, uint32_t addr) {
    asm volatile("ldmatrix.sync.aligned.m8n8.x4.shared.b16 {%0,%1,%2,%3}, [%4];"
                 : "=r"(r[0]), "=r"(r[1]), "=r"(r[2]), "=r"(r[3]) : "r"(addr));
}
__device__ __forceinline__ uint32_t hmul2u(uint32_t a, uint32_t b) {
    __half2 r = __hmul2(*(__half2*)&a, *(__half2*)&b);
    return *(uint32_t*)&r;
}
__device__ __forceinline__ void mma16816(float* c, const uint32_t* a,
                                         uint32_t b0, uint32_t b1) {
    asm volatile(
        "mma.sync.aligned.m16n8k16.row.col.f32.f16.f16.f32 "
        "{%0,%1,%2,%3}, {%4,%5,%6,%7}, {%8,%9}, {%0,%1,%2,%3};"
        : "+f"(c[0]), "+f"(c[1]), "+f"(c[2]), "+f"(c[3])
        : "r"(a[0]), "r"(a[1]), "r"(a[2]), "r"(a[3]), "r"(b0), "r"(b1));
}

// ---------------- prep ----------------
// Also zeroes out[] (exactly 2048*64 = 131072 elements = thread count) so the
// separate zero_out launch disappears and ncu's capture slot hits the main
// kernel.
__global__ void prep_H(const float* __restrict__ X, const float* __restrict__ W,
                       const float* __restrict__ bias, float* __restrict__ out) {
    int id = blockIdx.x * blockDim.x + threadIdx.x;  // 131072
    int i = id >> 6, f = id & 63;
    float s = 0.f;
#pragma unroll 8
    for (int c = 0; c < FIN; c++) s += X[i * FIN + c] * W[c * FOUT + f];
    s += bias[f];
    g_H[id] = s;
    // packed: [fq=f>>2][ipair=i>>1][fl=f&3][i&1]
    g_Hp[((f >> 2) << 13) + ((i >> 1) << 3) + ((f & 3) << 1) + (i & 1)] =
        __float2half_rn(s);
    out[id] = 0.f;
}
__global__ void prep_A(const float* __restrict__ A) {
    size_t id = (size_t)blockIdx.x * blockDim.x + threadIdx.x;
    float2 v = ((const float2*)A)[id];
    ((__half2*)g_Ah)[id] = __floats2half2_rn(v.x, v.y);
}
// tiled transpose + fp16 convert: g_mhT[k][i] = fp16(mh[i][k])
__global__ void prep_mhT(const float* __restrict__ mh) {
    __shared__ float t[32][33];
    const int bx = blockIdx.x * 32, by = blockIdx.y * 32;  // bx: k, by: i
    const int tx = threadIdx.x & 31, ty = threadIdx.x >> 5;
#pragma unroll
    for (int y = ty; y < 32; y += 8)
        t[y][tx] = mh[(size_t)(by + y) * NN + bx + tx];
    __syncthreads();
#pragma unroll
    for (int o = 0; o < 2; o++) {
        int idx = threadIdx.x + o * 256;
        int kr = idx >> 4, ip = idx & 15;
        __half2 v = __floats2half2_rn(t[ip * 2][kr], t[ip * 2 + 1][kr]);
        *(__half2*)&g_mhT[(size_t)(bx + kr) * NN + by + ip * 2] = v;
    }
}

// ---------------- main (persistent) ----------------
// grid = #SMs, 256 threads = 8 warps laid out 4 (j) x 2 (k).
__global__ void __launch_bounds__(256, 1)
interaction_main(const float* __restrict__ mf, float* __restrict__ out) {
    extern __shared__ char smem[];
    const uint32_t sb = smem_to_u32(smem);
    const int tid = threadIdx.x;
    const int lane = tid & 31, wid = tid >> 5;
    const int g = lane >> 2, tg = lane & 3;
    const int jbw = (wid & 3) * 32;    // warp j block (2 x m16)
    const int kbw = (wid >> 2) * 32;   // warp k block (4 x n8)
    const int cta = blockIdx.x, nsm = gridDim.x;

    const int ntiles = (cta < NTILES) ? ((NTILES - 1 - cta) / nsm + 1) : 0;
    const int total = ntiles * CPT;
    if (total == 0) return;

    // B ldmatrix lane mapping (validated R5): tile id = lane>>3,
    // bit0 -> i-half (col +16B), bit1 -> n8 tile (row group +8).
    // Two ldm4 per ks: rows kbw+0..15 and kbw+16..31.
    const int btl = lane >> 3;
    const int bn = kbw + ((btl >> 1) & 1) * 8 + (lane & 7);
    const uint32_t bcol0 = (uint32_t)((btl & 1) * 16);

    // ---- chunk loader: ALWAYS commits a group (possibly empty) so
    // wait_group counts are exact (groups complete in commit order).
    auto issue = [&](int gc) {
        if (gc < total) {
            const int s = gc >> 4, c = gc & 15;
            const int t = cta + s * nsm;
            const int jb = (t >> 9) * JT;
            const int kb = ((t >> 4) & 31) * KT;
            const int fq = t & 15;
            const uint32_t base = sb + (uint32_t)(gc & 3) * STAGE;
            const int ibase = c * IC;
#pragma unroll
            for (int o = 0; o < 8; o++) {
                int idx = tid + o * 256, j = idx >> 4, cc = idx & 15;
                cp16(base + ST_A + j * 256 + ((cc * 16) ^ ((j & 7) * 16)),
                     g_Ah + (size_t)(jb + j) * NN + ibase + cc * 8);
            }
#pragma unroll
            for (int o = 0; o < 4; o++) {
                int idx = tid + o * 256, n = idx >> 4, cc = idx & 15;
                cp16(base + ST_MH + n * 256 + ((cc * 16) ^ ((n & 7) * 16)),
                     g_mhT + (size_t)(kb + n) * NN + ibase + cc * 8);
            }
            if (tid < 64) {
                // packed H: 64 ipairs x 16B for this chunk's i-range
                cp16(base + ST_H + tid * 16,
                     g_Hp + ((size_t)fq << 13) + (size_t)((ibase >> 1) + tid) * 8);
            }
            if (c == 0 && tid < 64) {
                // Hk [64][4] fp32, parity buffer s&1 (>=15-barrier separation)
                cp16(sb + SM_HK + (uint32_t)(s & 1) * 1024 + tid * 16,
                     g_H + (kb + tid) * FOUT + fq * FB);
            }
        }
        cp_commit();
    };

    issue(0);
    issue(1);

    float acc[FB][2][4][4];            // 128 regs
    for (int s = 0; s < ntiles; s++) {
        const int t = cta + s * nsm;
        const int jbase = (t >> 9) * JT;
        const int kb0 = ((t >> 4) & 31) * KT;
        const int f0 = (t & 15) * FB;

#pragma unroll
        for (int f = 0; f < FB; f++)
#pragma unroll
            for (int mt = 0; mt < 2; mt++)
#pragma unroll
                for (int nt = 0; nt < 4; nt++)
#pragma unroll
                    for (int e = 0; e < 4; e++) acc[f][mt][nt][e] = 0.f;

        for (int cp = 0; cp < CPT / 2; cp++) {
            const int gc = s * CPT + cp * 2;
            // One prefetch on the critical path; groups complete in order,
            // so <=1 outstanding => chunks gc, gc+1 both arrived.
            issue(gc + 2);
            asm volatile("cp.async.wait_group 1;" ::: "memory");
            __syncthreads();   // chunks gc, gc+1 visible; all warps aligned

#pragma unroll
            for (int half = 0; half < 2; half++) {
                if (half == 1) issue(gc + 3);
                // ^ off the critical path: overlaps half-0 compute. Ring-safe:
                // writer stage (gc+3)&3 vs live readers gc&3/(gc+1)&3.
                const int st = (gc + half) & 3;
                const uint32_t abase = sb + (uint32_t)st * STAGE + ST_A;
                const uint32_t mbase = sb + (uint32_t)st * STAGE + ST_MH;
                const uint32_t hbase = sb + (uint32_t)st * STAGE + ST_H;

#pragma unroll
                for (int ks = 0; ks < 8; ks++) {
                    // B path first (longer chain: ldm -> HMUL2 -> mma)
                    uint32_t bfr0[4], bfr1[4];
                    ldm4(bfr0, mbase + bn * 256 +
                                   ((ks * 32 + bcol0) ^ ((bn & 7) * 16)));
                    ldm4(bfr1, mbase + (bn + 16) * 256 +
                                   ((ks * 32 + bcol0) ^ (((bn + 16) & 7) * 16)));
                    uint4 h0 = lds128(hbase + (ks * 8 + tg) * 16);
                    uint4 h1 = lds128(hbase + (ks * 8 + tg + 4) * 16);

                    uint32_t a[2][4];
#pragma unroll
                    for (int mt = 0; mt < 2; mt++) {
                        int jr = jbw + mt * 16 + (lane & 15);
                        ldm4(a[mt], abase + jr * 256 +
                               ((((lane >> 4) * 16) + ks * 32) ^ ((jr & 7) * 16)));
                    }
                    const uint32_t* hp0 = (const uint32_t*)&h0;
                    const uint32_t* hp1 = (const uint32_t*)&h1;
#pragma unroll
                    for (int f = 0; f < FB; f++) {
                        // nt tiles: 0,1 from bfr0 (rows kbw..kbw+15),
                        //           2,3 from bfr1 (rows kbw+16..kbw+31)
                        uint32_t b00 = hmul2u(bfr0[0], hp0[f]);
                        uint32_t b01 = hmul2u(bfr0[1], hp1[f]);
                        uint32_t b10 = hmul2u(bfr0[2], hp0[f]);
                        uint32_t b11 = hmul2u(bfr0[3], hp1[f]);
                        uint32_t b20 = hmul2u(bfr1[0], hp0[f]);
                        uint32_t b21 = hmul2u(bfr1[1], hp1[f]);
                        uint32_t b30 = hmul2u(bfr1[2], hp0[f]);
                        uint32_t b31 = hmul2u(bfr1[3], hp1[f]);
#pragma unroll
                        for (int mt = 0; mt < 2; mt++) {
                            mma16816(acc[f][mt][0], a[mt], b00, b01);
                            mma16816(acc[f][mt][1], a[mt], b10, b11);
                            mma16816(acc[f][mt][2], a[mt], b20, b21);
                            mma16816(acc[f][mt][3], a[mt], b30, b31);
                        }
                    }
                }
            }
        }

        // ---- epilogue (no barrier): float2 mf LDG (L2-hot), Hk parity smem
        const float* Hks = (const float*)(smem + SM_HK + (size_t)(s & 1) * 1024);
#pragma unroll
        for (int mt = 0; mt < 2; mt++)
#pragma unroll
            for (int h2 = 0; h2 < 2; h2++) {
                const int j = jbw + mt * 16 + g + 8 * h2;
                float s4[FB] = {0.f, 0.f, 0.f, 0.f};
#pragma unroll
                for (int nt = 0; nt < 4; nt++) {
                    const int k0 = kbw + nt * 8 + tg * 2;
                    const float2 mp =
                        *(const float2*)&mf[(size_t)(jbase + j) * NN + kb0 + k0];
#pragma unroll
                    for (int e = 0; e < 2; e++) {
                        const float mv = e ? mp.y : mp.x;
                        const float4 hk = *(const float4*)&Hks[(k0 + e) * 4];
                        s4[0] += acc[0][mt][nt][h2 * 2 + e] * mv * hk.x;
                        s4[1] += acc[1][mt][nt][h2 * 2 + e] * mv * hk.y;
                        s4[2] += acc[2][mt][nt][h2 * 2 + e] * mv * hk.z;
                        s4[3] += acc[3][mt][nt][h2 * 2 + e] * mv * hk.w;
                    }
                }
#pragma unroll
                for (int f = 0; f < FB; f++) {
                    float v = s4[f];
                    v += __shfl_xor_sync(0xffffffffu, v, 1);
                    v += __shfl_xor_sync(0xffffffffu, v, 2);
                    if (tg == 0)
                        atomicAdd(&out[(size_t)(jbase + j) * FOUT + f0 + f], v);
                }
            }
    }
}

// ---------------- launch ----------------
extern "C" void kernel_launch(void* const* d_in, const int* in_sizes, int n_in,
                              void* d_out, int out_size) {
    const float* X  = (const float*)d_in[0];
    const float* A  = (const float*)d_in[1];
    const float* mf = (const float*)d_in[2];
    const float* mh = (const float*)d_in[3];
    const float* W  = (const float*)d_in[4];
    const float* b  = (const float*)d_in[5];
    float* out = (float*)d_out;

    int dev = 0, nsm = 148;
    cudaGetDevice(&dev);
    cudaDeviceGetAttribute(&nsm, cudaDevAttrMultiProcessorCount, dev);

    cudaFuncSetAttribute(interaction_main,
                         cudaFuncAttributeMaxDynamicSharedMemorySize, SMEM_TOTAL);

    prep_H<<<256, 512>>>(X, W, b, out);   // also zeroes out
    prep_A<<<4096, 512>>>(A);
    prep_mhT<<<dim3(64, 64), 256>>>(mh);
    interaction_main<<<nsm, 256, SMEM_TOTAL>>>(mf, out);
}

// round 16
// speedup vs baseline: 1.0433x; 1.0433x over previous
#include <cuda_runtime.h>
#include <cuda_fp16.h>
#include <cstdint>

// N=2048, F_IN=128, F_OUT=64
//   H = X@W + b
//   out[j,f] = sum_k mf[j,k]*H[k,f]* (sum_i A[j,i]*H[i,f]*mh[i,k])
// Per f: G_f = A . diag(h_f) . mh  (fp16 mma.sync, fp32 accum), k contracted
// immediately in the epilogue. mh pre-transposed fp16 [k][i]; B frags via
// ldmatrix.x4; H folded via HMUL2 (packed-H: 2x LDS128 per ks).
// R16 = R15 with the deadlock fixed: cp.async.mbarrier.arrive ->
// cp.async.mbarrier.arrive.NOINC. (Default form increments pending count by 1
// before arriving -- net-neutral, so the full barrier never completed a phase.
// .noinc + init count 256 completes after exactly one arrive per thread.)
// Pipeline: per-stage mbarrier producer/consumer ring, warps slip up to 4
// chunks instead of realigning at 880 block barriers (R14 ncu: tensor=77.4%,
// ~2170 idle cyc per barrier pair = the target).

#define NN   2048
#define FIN  128
#define FOUT 64

#define JT 128
#define KT 64
#define FB 4
#define IC 128
#define CPT 16            // chunks per tile
#define NTILES 8192       // 16 jt * 32 kt * 16 fq

// ---- smem: 4 ring stages {A, mhT, Hp} + parity Hk + mbarriers ----
#define ST_A   0          // [128 j][128 i] fp16, 256B rows, XOR16 swz = 32768
#define ST_MH  32768      // [64 k][128 i] fp16                       = 16384
#define ST_H   49152      // [64 ipair][4 f] half2 (16B/ipair)        = 1024
#define STAGE  50176
#define NSTG   4
#define SM_HK  (NSTG * STAGE)          // 200704; 2 x [64][4] fp32 = 2048
#define SM_MB  (SM_HK + 2048)          // 202752: full[4] @ +0, empty[4] @ +32
#define SMEM_TOTAL (SM_MB + 128)       // 202880

__device__ float  g_H[NN * FOUT];          // fp32 H for epilogue
__device__ __half g_Hp[16 * 1024 * 8];     // packed [fq][ipair][f][2] fp16
__device__ __half g_Ah[(size_t)NN * NN];   // adjacency fp16 [j][i]
__device__ __half g_mhT[(size_t)NN * NN];  // mask_hadamard fp16 transposed [k][i]

// ---------------- helpers ----------------
__device__ __forceinline__ uint32_t smem_to_u32(const void* p) {
    uint32_t a;
    asm("{ .reg .u64 t; cvta.to.shared.u64 t, %1; cvt.u32.u64 %0, t; }"
        : "=r"(a) : "l"(p));
    return a;
}
__device__ __forceinline__ void cp16(uint32_t dst, const void* src) {
    asm volatile("cp.async.cg.shared.global [%0], [%1], 16;" :: "r"(dst), "l"(src));
}
// .noinc: does NOT bump pending count -> with init count = 256 the phase
// completes after one arrive per thread (the default form is net-neutral and
// deadlocks this scheme -- R15's bug).
__device__ __forceinline__ void cp_async_mbar_arrive_noinc(uint32_t mbar) {
    asm volatile("cp.async.mbarrier.arrive.noinc.shared.b64 [%0];"
                 :: "r"(mbar) : "memory");
}
#define MBARRIER_INIT(mbar, count)                                     \
    asm volatile("mbarrier.init.shared.b64 [%0], %1;"                  \
                 :: "r"((uint32_t)(mbar)), "r"((uint32_t)(count)) : "memory")
#define MBARRIER_ARRIVE(mbar)                                          \
    asm volatile("mbarrier.arrive.shared.b64 _, [%0];"                 \
                 :: "r"((uint32_t)(mbar)) : "memory")
#define MBARRIER_WAIT_PARITY(mbar_addr, phase_parity) do {                                   \
    uint32_t _mbar = (uint32_t)(mbar_addr);                                                  \
    uint32_t _parity = (uint32_t)(phase_parity);                                             \
    uint32_t _done;                                                                          \
    asm volatile(                                                                            \
        "{\n\t.reg .pred p;\n\t"                                                             \
        "mbarrier.try_wait.parity.acquire.cta.shared::cta.b64 p, [%1], %2;\n\t"              \
        "selp.b32 %0, 1, 0, p;\n\t}"                                                         \
        : "=r"(_done) : "r"(_mbar), "r"(_parity) : "memory");                                \
    if (!_done) {                                                                            \
        asm volatile(                                                                        \
            "{\n\t.reg .pred P1;\n\t"                                                        \
            "WAIT_LOOP_%=:\n\t"                                                              \
            "mbarrier.try_wait.parity.acquire.cta.shared::cta.b64 P1, [%0], %1, 0x989680;\n\t" \
            "@P1 bra.uni WAIT_DONE_%=;\n\t"                                                  \
            "bra.uni WAIT_LOOP_%=;\n\t"                                                      \
            "WAIT_DONE_%=:\n\t}"                                                             \
            :: "r"(_mbar), "r"(_parity) : "memory");                                         \
    }                                                                                        \
} while (0)

__device__ __forceinline__ uint4 lds128(uint32_t addr) {
    uint4 v;
    asm volatile("ld.shared.v4.b32 {%0,%1,%2,%3}, [%4];"
                 : "=r"(v.x), "=r"(v.y), "=r"(v.z), "=r"(v.w) : "r"(addr));
    return v;
}
__device__ __forceinline__ void ldm4(uint32_t* r, uint32_t addr) {
    asm volatile("ldmatrix.sync.aligned.m8n8.x4.shared.b16 {%0,%1,%2,%3}, [%4];"
                 : "=r"(r[0]), "=r"(r[1]), "=r"(r[2]), "=r"(r[3]) : "r"(addr));
}
__device__ __forceinline__ uint32_t hmul2u(uint32_t a, uint32_t b) {
    __half2 r = __hmul2(*(__half2*)&a, *(__half2*)&b);
    return *(uint32_t*)&r;
}
__device__ __forceinline__ void mma16816(float* c, const uint32_t* a,
                                         uint32_t b0, uint32_t b1) {
    asm volatile(
        "mma.sync.aligned.m16n8k16.row.col.f32.f16.f16.f32 "
        "{%0,%1,%2,%3}, {%4,%5,%6,%7}, {%8,%9}, {%0,%1,%2,%3};"
        : "+f"(c[0]), "+f"(c[1]), "+f"(c[2]), "+f"(c[3])
        : "r"(a[0]), "r"(a[1]), "r"(a[2]), "r"(a[3]), "r"(b0), "r"(b1));
}

// ---------------- prep ----------------
// Also zeroes out[] so the ncu capture slot stays on interaction_main.
__global__ void prep_H(const float* __restrict__ X, const float* __restrict__ W,
                       const float* __restrict__ bias, float* __restrict__ out) {
    int id = blockIdx.x * blockDim.x + threadIdx.x;  // 131072
    int i = id >> 6, f = id & 63;
    float s = 0.f;
#pragma unroll 8
    for (int c = 0; c < FIN; c++) s += X[i * FIN + c] * W[c * FOUT + f];
    s += bias[f];
    g_H[id] = s;
    g_Hp[((f >> 2) << 13) + ((i >> 1) << 3) + ((f & 3) << 1) + (i & 1)] =
        __float2half_rn(s);
    out[id] = 0.f;
}
__global__ void prep_A(const float* __restrict__ A) {
    size_t id = (size_t)blockIdx.x * blockDim.x + threadIdx.x;
    float2 v = ((const float2*)A)[id];
    ((__half2*)g_Ah)[id] = __floats2half2_rn(v.x, v.y);
}
// tiled transpose + fp16 convert: g_mhT[k][i] = fp16(mh[i][k])
__global__ void prep_mhT(const float* __restrict__ mh) {
    __shared__ float t[32][33];
    const int bx = blockIdx.x * 32, by = blockIdx.y * 32;  // bx: k, by: i
    const int tx = threadIdx.x & 31, ty = threadIdx.x >> 5;
#pragma unroll
    for (int y = ty; y < 32; y += 8)
        t[y][tx] = mh[(size_t)(by + y) * NN + bx + tx];
    __syncthreads();
#pragma unroll
    for (int o = 0; o < 2; o++) {
        int idx = threadIdx.x + o * 256;
        int kr = idx >> 4, ip = idx & 15;
        __half2 v = __floats2half2_rn(t[ip * 2][kr], t[ip * 2 + 1][kr]);
        *(__half2*)&g_mhT[(size_t)(bx + kr) * NN + by + ip * 2] = v;
    }
}

// ---------------- main (persistent) ----------------
// grid = #SMs, 256 threads = 8 warps laid out 2 (j) x 4 (k).
__global__ void __launch_bounds__(256, 1)
interaction_main(const float* __restrict__ mf, float* __restrict__ out) {
    extern __shared__ char smem[];
    const uint32_t sb = smem_to_u32(smem);
    const int tid = threadIdx.x;
    const int lane = tid & 31, wid = tid >> 5;
    const int g = lane >> 2, tg = lane & 3;
    const int jbw = (wid & 1) * 64;    // warp j block (4 x m16)
    const int kbw = (wid >> 1) * 16;   // warp k block (2 x n8)
    const int cta = blockIdx.x, nsm = gridDim.x;

    const int ntiles = (cta < NTILES) ? ((NTILES - 1 - cta) / nsm + 1) : 0;
    const int total = ntiles * CPT;
    if (total == 0) return;

    const uint32_t mb_full = sb + SM_MB;        // 4 x 8B
    const uint32_t mb_empty = sb + SM_MB + 32;  // 4 x 8B
    if (tid == 0) {
#pragma unroll
        for (int st = 0; st < NSTG; st++) {
            MBARRIER_INIT(mb_full + st * 8, 256);  // one .noinc arrive per thread
            MBARRIER_INIT(mb_empty + st * 8, 8);   // one arrive per warp
        }
    }
    __syncthreads();  // the only block barrier in the kernel

    // B ldmatrix lane mapping (validated R5): tile id = lane>>3,
    // bit0 -> i-half (col +16B), bit1 -> n8 tile (row group +8)
    const int btl = lane >> 3;
    const int bn = kbw + ((btl >> 1) & 1) * 8 + (lane & 7);
    const uint32_t bcol0 = (uint32_t)((btl & 1) * 16);

    // ---- chunk loader (producer side) ----
    // empty-wait parity for use u = gc>>2 is (u-1)&1 = ((gc>>2)&1)^1; first
    // use (u=0) passes immediately on a fresh barrier (phase bit 0 != 1).
    auto issue = [&](int gc) {
        if (gc >= total) return;
        const int st = gc & 3;
        MBARRIER_WAIT_PARITY(mb_empty + st * 8, ((gc >> 2) & 1) ^ 1);
        const int s = gc >> 4, c = gc & 15;
        const int t = cta + s * nsm;
        const int jb = (t >> 9) * JT;
        const int kb = ((t >> 4) & 31) * KT;
        const int fq = t & 15;
        const uint32_t base = sb + (uint32_t)st * STAGE;
        const int ibase = c * IC;
#pragma unroll
        for (int o = 0; o < 8; o++) {
            int idx = tid + o * 256, j = idx >> 4, cc = idx & 15;
            cp16(base + ST_A + j * 256 + ((cc * 16) ^ ((j & 7) * 16)),
                 g_Ah + (size_t)(jb + j) * NN + ibase + cc * 8);
        }
#pragma unroll
        for (int o = 0; o < 4; o++) {
            int idx = tid + o * 256, n = idx >> 4, cc = idx & 15;
            cp16(base + ST_MH + n * 256 + ((cc * 16) ^ ((n & 7) * 16)),
                 g_mhT + (size_t)(kb + n) * NN + ibase + cc * 8);
        }
        if (tid < 64) {
            cp16(base + ST_H + tid * 16,
                 g_Hp + ((size_t)fq << 13) + (size_t)((ibase >> 1) + tid) * 8);
        }
        if (c == 0 && tid < 64) {
            // Hk [64][4] fp32, parity buffer s&1. Safe: any warp issuing tile
            // s+2 chunk-0 implies (via full-barrier coupling, skew <= 2
            // chunks) every warp is >= tile s+1 c=11, i.e. past tile s's
            // epilogue read of this buffer.
            cp16(sb + SM_HK + (uint32_t)(s & 1) * 1024 + tid * 16,
                 g_H + (kb + tid) * FOUT + fq * FB);
        }
        cp_async_mbar_arrive_noinc(mb_full + st * 8);
    };

    issue(0);
    issue(1);

    float acc[FB][4][2][4];            // 128 regs
    for (int s = 0; s < ntiles; s++) {
        const int t = cta + s * nsm;
        const int jbase = (t >> 9) * JT;
        const int kb0 = ((t >> 4) & 31) * KT;
        const int f0 = (t & 15) * FB;

#pragma unroll
        for (int f = 0; f < FB; f++)
#pragma unroll
            for (int mt = 0; mt < 4; mt++)
#pragma unroll
                for (int nt = 0; nt < 2; nt++)
#pragma unroll
                    for (int e = 0; e < 4; e++) acc[f][mt][nt][e] = 0.f;

        for (int c = 0; c < CPT; c++) {
            const int gc = s * CPT + c;
            issue(gc + 2);   // prefetch (producer waits its own empty barrier)

            const int st = gc & 3;
            // consumer waits completion of use u = gc>>2: parity u&1
            MBARRIER_WAIT_PARITY(mb_full + st * 8, (gc >> 2) & 1);

            const uint32_t abase = sb + (uint32_t)st * STAGE + ST_A;
            const uint32_t mbase = sb + (uint32_t)st * STAGE + ST_MH;
            const uint32_t hbase = sb + (uint32_t)st * STAGE + ST_H;

#pragma unroll
            for (int ks = 0; ks < 8; ks++) {
                // B path first (longer chain: ldm -> HMUL2 -> mma)
                uint32_t bfr[4];
                ldm4(bfr, mbase + bn * 256 +
                              ((ks * 32 + bcol0) ^ ((bn & 7) * 16)));
                uint4 h0 = lds128(hbase + (ks * 8 + tg) * 16);
                uint4 h1 = lds128(hbase + (ks * 8 + tg + 4) * 16);

                uint32_t a[4][4];
#pragma unroll
                for (int mt = 0; mt < 4; mt++) {
                    int jr = jbw + mt * 16 + (lane & 15);
                    ldm4(a[mt], abase + jr * 256 +
                           ((((lane >> 4) * 16) + ks * 32) ^ ((jr & 7) * 16)));
                }
                const uint32_t* hp0 = (const uint32_t*)&h0;
                const uint32_t* hp1 = (const uint32_t*)&h1;
#pragma unroll
                for (int f = 0; f < FB; f++) {
                    uint32_t b00 = hmul2u(bfr[0], hp0[f]);
                    uint32_t b01 = hmul2u(bfr[1], hp1[f]);
                    uint32_t b10 = hmul2u(bfr[2], hp0[f]);
                    uint32_t b11 = hmul2u(bfr[3], hp1[f]);
#pragma unroll
                    for (int mt = 0; mt < 4; mt++) {
                        mma16816(acc[f][mt][0], a[mt], b00, b01);
                        mma16816(acc[f][mt][1], a[mt], b10, b11);
                    }
                }
            }
            // consumer done with stage st: every lane's loads fed an issued
            // mma (completed), so after __syncwarp the warp's reads are done.
            __syncwarp();
            if (lane == 0) MBARRIER_ARRIVE(mb_empty + st * 8);
        }

        // ---- epilogue (no block barrier): float2 mf LDG, Hk parity smem
        const float* Hks = (const float*)(smem + SM_HK + (size_t)(s & 1) * 1024);
#pragma unroll
        for (int mt = 0; mt < 4; mt++)
#pragma unroll
            for (int h2 = 0; h2 < 2; h2++) {
                const int j = jbw + mt * 16 + g + 8 * h2;
                float s4[FB] = {0.f, 0.f, 0.f, 0.f};
#pragma unroll
                for (int nt = 0; nt < 2; nt++) {
                    const int k0 = kbw + nt * 8 + tg * 2;
                    const float2 mp =
                        *(const float2*)&mf[(size_t)(jbase + j) * NN + kb0 + k0];
#pragma unroll
                    for (int e = 0; e < 2; e++) {
                        const float mv = e ? mp.y : mp.x;
                        const float4 hk = *(const float4*)&Hks[(k0 + e) * 4];
                        s4[0] += acc[0][mt][nt][h2 * 2 + e] * mv * hk.x;
                        s4[1] += acc[1][mt][nt][h2 * 2 + e] * mv * hk.y;
                        s4[2] += acc[2][mt][nt][h2 * 2 + e] * mv * hk.z;
                        s4[3] += acc[3][mt][nt][h2 * 2 + e] * mv * hk.w;
                    }
                }
#pragma unroll
                for (int f = 0; f < FB; f++) {
                    float v = s4[f];
                    v += __shfl_xor_sync(0xffffffffu, v, 1);
                    v += __shfl_xor_sync(0xffffffffu, v, 2);
                    if (tg == 0)
                        atomicAdd(&out[(size_t)(jbase + j) * FOUT + f0 + f], v);
                }
            }
    }
}

// ---------------- launch ----------------
extern "C" void kernel_launch(void* const* d_in, const int* in_sizes, int n_in,
                              void* d_out, int out_size) {
    const float* X  = (const float*)d_in[0];
    const float* A  = (const float*)d_in[1];
    const float* mf = (const float*)d_in[2];
    const float* mh = (const float*)d_in[3];
    const float* W  = (const float*)d_in[4];
    const float* b  = (const float*)d_in[5];
    float* out = (float*)d_out;

    int dev = 0, nsm = 148;
    cudaGetDevice(&dev);
    cudaDeviceGetAttribute(&nsm, cudaDevAttrMultiProcessorCount, dev);

    cudaFuncSetAttribute(interaction_main,
                         cudaFuncAttributeMaxDynamicSharedMemorySize, SMEM_TOTAL);

    prep_H<<<256, 512>>>(X, W, b, out);   // also zeroes out
    prep_A<<<4096, 512>>>(A);
    prep_mhT<<<dim3(64, 64), 256>>>(mh);
    interaction_main<<<nsm, 256, SMEM_TOTAL>>>(mf, out);
}

// round 17
// speedup vs baseline: 1.0570x; 1.0131x over previous
#include <cuda_runtime.h>
#include <cuda_fp16.h>
#include <cstdint>

// N=2048, F_IN=128, F_OUT=64
//   H = X@W + b
//   out[j,f] = sum_k mf[j,k]*H[k,f]* (sum_i A[j,i]*H[i,f]*mh[i,k])
// Per f: G_f = A . diag(h_f) . mh  (fp16 mma.sync, fp32 accum), k contracted
// immediately in the epilogue. mh pre-transposed fp16 [k][i]; B frags via
// ldmatrix.x4; H folded via HMUL2 (packed-H: 2x LDS128 per ks).
// R17 = R16 (persistent CTAs + mbarrier producer/consumer ring, .noinc
// cp.async arrives) with ONE change: the producer call issue(gc+2) moves from
// the chunk head into the middle of the ks-unrolled compute (ks==2), so the
// ~13-cp16 burst + empty-wait overlap >=512 queued tensor cycles instead of
// sitting on the critical path before each chunk's first mma.

#define NN   2048
#define FIN  128
#define FOUT 64

#define JT 128
#define KT 64
#define FB 4
#define IC 128
#define CPT 16            // chunks per tile
#define NTILES 8192       // 16 jt * 32 kt * 16 fq

// ---- smem: 4 ring stages {A, mhT, Hp} + parity Hk + mbarriers ----
#define ST_A   0          // [128 j][128 i] fp16, 256B rows, XOR16 swz = 32768
#define ST_MH  32768      // [64 k][128 i] fp16                       = 16384
#define ST_H   49152      // [64 ipair][4 f] half2 (16B/ipair)        = 1024
#define STAGE  50176
#define NSTG   4
#define SM_HK  (NSTG * STAGE)          // 200704; 2 x [64][4] fp32 = 2048
#define SM_MB  (SM_HK + 2048)          // 202752: full[4] @ +0, empty[4] @ +32
#define SMEM_TOTAL (SM_MB + 128)       // 202880

__device__ float  g_H[NN * FOUT];          // fp32 H for epilogue
__device__ __half g_Hp[16 * 1024 * 8];     // packed [fq][ipair][f][2] fp16
__device__ __half g_Ah[(size_t)NN * NN];   // adjacency fp16 [j][i]
__device__ __half g_mhT[(size_t)NN * NN];  // mask_hadamard fp16 transposed [k][i]

// ---------------- helpers ----------------
__device__ __forceinline__ uint32_t smem_to_u32(const void* p) {
    uint32_t a;
    asm("{ .reg .u64 t; cvta.to.shared.u64 t, %1; cvt.u32.u64 %0, t; }"
        : "=r"(a) : "l"(p));
    return a;
}
__device__ __forceinline__ void cp16(uint32_t dst, const void* src) {
    asm volatile("cp.async.cg.shared.global [%0], [%1], 16;" :: "r"(dst), "l"(src));
}
// .noinc: does NOT bump pending count -> with init count = 256 the phase
// completes after one arrive per thread (default form is net-neutral: R15 bug).
__device__ __forceinline__ void cp_async_mbar_arrive_noinc(uint32_t mbar) {
    asm volatile("cp.async.mbarrier.arrive.noinc.shared.b64 [%0];"
                 :: "r"(mbar) : "memory");
}
#define MBARRIER_INIT(mbar, count)                                     \
    asm volatile("mbarrier.init.shared.b64 [%0], %1;"                  \
                 :: "r"((uint32_t)(mbar)), "r"((uint32_t)(count)) : "memory")
#define MBARRIER_ARRIVE(mbar)                                          \
    asm volatile("mbarrier.arrive.shared.b64 _, [%0];"                 \
                 :: "r"((uint32_t)(mbar)) : "memory")
#define MBARRIER_WAIT_PARITY(mbar_addr, phase_parity) do {                                   \
    uint32_t _mbar = (uint32_t)(mbar_addr);                                                  \
    uint32_t _parity = (uint32_t)(phase_parity);                                             \
    uint32_t _done;                                                                          \
    asm volatile(                                                                            \
        "{\n\t.reg .pred p;\n\t"                                                             \
        "mbarrier.try_wait.parity.acquire.cta.shared::cta.b64 p, [%1], %2;\n\t"              \
        "selp.b32 %0, 1, 0, p;\n\t}"                                                         \
        : "=r"(_done) : "r"(_mbar), "r"(_parity) : "memory");                                \
    if (!_done) {                                                                            \
        asm volatile(                                                                        \
            "{\n\t.reg .pred P1;\n\t"                                                        \
            "WAIT_LOOP_%=:\n\t"                                                              \
            "mbarrier.try_wait.parity.acquire.cta.shared::cta.b64 P1, [%0], %1, 0x989680;\n\t" \
            "@P1 bra.uni WAIT_DONE_%=;\n\t"                                                  \
            "bra.uni WAIT_LOOP_%=;\n\t"                                                      \
            "WAIT_DONE_%=:\n\t}"                                                             \
            :: "r"(_mbar), "r"(_parity) : "memory");                                         \
    }                                                                                        \
} while (0)

__device__ __forceinline__ uint4 lds128(uint32_t addr) {
    uint4 v;
    asm volatile("ld.shared.v4.b32 {%0,%1,%2,%3}, [%4];"
                 : "=r"(v.x), "=r"(v.y), "=r"(v.z), "=r"(v.w) : "r"(addr));
    return v;
}
__device__ __forceinline__ void ldm4(uint32_t* r, uint32_t addr) {
    asm volatile("ldmatrix.sync.aligned.m8n8.x4.shared.b16 {%0,%1,%2,%3}, [%4];"
                 : "=r"(r[0]), "=r"(r[1]), "=r"(r[2]), "=r"(r[3]) : "r"(addr));
}
__device__ __forceinline__ uint32_t hmul2u(uint32_t a, uint32_t b) {
    __half2 r = __hmul2(*(__half2*)&a, *(__half2*)&b);
    return *(uint32_t*)&r;
}
__device__ __forceinline__ void mma16816(float* c, const uint32_t* a,
                                         uint32_t b0, uint32_t b1) {
    asm volatile(
        "mma.sync.aligned.m16n8k16.row.col.f32.f16.f16.f32 "
        "{%0,%1,%2,%3}, {%4,%5,%6,%7}, {%8,%9}, {%0,%1,%2,%3};"
        : "+f"(c[0]), "+f"(c[1]), "+f"(c[2]), "+f"(c[3])
        : "r"(a[0]), "r"(a[1]), "r"(a[2]), "r"(a[3]), "r"(b0), "r"(b1));
}

// ---------------- prep ----------------
// Also zeroes out[] so the ncu capture slot stays on interaction_main.
__global__ void prep_H(const float* __restrict__ X, const float* __restrict__ W,
                       const float* __restrict__ bias, float* __restrict__ out) {
    int id = blockIdx.x * blockDim.x + threadIdx.x;  // 131072
    int i = id >> 6, f = id & 63;
    float s = 0.f;
#pragma unroll 8
    for (int c = 0; c < FIN; c++) s += X[i * FIN + c] * W[c * FOUT + f];
    s += bias[f];
    g_H[id] = s;
    g_Hp[((f >> 2) << 13) + ((i >> 1) << 3) + ((f & 3) << 1) + (i & 1)] =
        __float2half_rn(s);
    out[id] = 0.f;
}
__global__ void prep_A(const float* __restrict__ A) {
    size_t id = (size_t)blockIdx.x * blockDim.x + threadIdx.x;
    float2 v = ((const float2*)A)[id];
    ((__half2*)g_Ah)[id] = __floats2half2_rn(v.x, v.y);
}
// tiled transpose + fp16 convert: g_mhT[k][i] = fp16(mh[i][k])
__global__ void prep_mhT(const float* __restrict__ mh) {
    __shared__ float t[32][33];
    const int bx = blockIdx.x * 32, by = blockIdx.y * 32;  // bx: k, by: i
    const int tx = threadIdx.x & 31, ty = threadIdx.x >> 5;
#pragma unroll
    for (int y = ty; y < 32; y += 8)
        t[y][tx] = mh[(size_t)(by + y) * NN + bx + tx];
    __syncthreads();
#pragma unroll
    for (int o = 0; o < 2; o++) {
        int idx = threadIdx.x + o * 256;
        int kr = idx >> 4, ip = idx & 15;
        __half2 v = __floats2half2_rn(t[ip * 2][kr], t[ip * 2 + 1][kr]);
        *(__half2*)&g_mhT[(size_t)(bx + kr) * NN + by + ip * 2] = v;
    }
}

// ---------------- main (persistent) ----------------
// grid = #SMs, 256 threads = 8 warps laid out 2 (j) x 4 (k).
__global__ void __launch_bounds__(256, 1)
interaction_main(const float* __restrict__ mf, float* __restrict__ out) {
    extern __shared__ char smem[];
    const uint32_t sb = smem_to_u32(smem);
    const int tid = threadIdx.x;
    const int lane = tid & 31, wid = tid >> 5;
    const int g = lane >> 2, tg = lane & 3;
    const int jbw = (wid & 1) * 64;    // warp j block (4 x m16)
    const int kbw = (wid >> 1) * 16;   // warp k block (2 x n8)
    const int cta = blockIdx.x, nsm = gridDim.x;

    const int ntiles = (cta < NTILES) ? ((NTILES - 1 - cta) / nsm + 1) : 0;
    const int total = ntiles * CPT;
    if (total == 0) return;

    const uint32_t mb_full = sb + SM_MB;        // 4 x 8B
    const uint32_t mb_empty = sb + SM_MB + 32;  // 4 x 8B
    if (tid == 0) {
#pragma unroll
        for (int st = 0; st < NSTG; st++) {
            MBARRIER_INIT(mb_full + st * 8, 256);  // one .noinc arrive per thread
            MBARRIER_INIT(mb_empty + st * 8, 8);   // one arrive per warp
        }
    }
    __syncthreads();  // the only block barrier in the kernel

    // B ldmatrix lane mapping (validated R5): tile id = lane>>3,
    // bit0 -> i-half (col +16B), bit1 -> n8 tile (row group +8)
    const int btl = lane >> 3;
    const int bn = kbw + ((btl >> 1) & 1) * 8 + (lane & 7);
    const uint32_t bcol0 = (uint32_t)((btl & 1) * 16);

    // ---- chunk loader (producer side) ----
    // empty-wait parity for use u = gc>>2 is (u-1)&1 = ((gc>>2)&1)^1; first
    // use (u=0) passes immediately on a fresh barrier.
    auto issue = [&](int gc) {
        if (gc >= total) return;
        const int st = gc & 3;
        MBARRIER_WAIT_PARITY(mb_empty + st * 8, ((gc >> 2) & 1) ^ 1);
        const int s = gc >> 4, c = gc & 15;
        const int t = cta + s * nsm;
        const int jb = (t >> 9) * JT;
        const int kb = ((t >> 4) & 31) * KT;
        const int fq = t & 15;
        const uint32_t base = sb + (uint32_t)st * STAGE;
        const int ibase = c * IC;
#pragma unroll
        for (int o = 0; o < 8; o++) {
            int idx = tid + o * 256, j = idx >> 4, cc = idx & 15;
            cp16(base + ST_A + j * 256 + ((cc * 16) ^ ((j & 7) * 16)),
                 g_Ah + (size_t)(jb + j) * NN + ibase + cc * 8);
        }
#pragma unroll
        for (int o = 0; o < 4; o++) {
            int idx = tid + o * 256, n = idx >> 4, cc = idx & 15;
            cp16(base + ST_MH + n * 256 + ((cc * 16) ^ ((n & 7) * 16)),
                 g_mhT + (size_t)(kb + n) * NN + ibase + cc * 8);
        }
        if (tid < 64) {
            cp16(base + ST_H + tid * 16,
                 g_Hp + ((size_t)fq << 13) + (size_t)((ibase >> 1) + tid) * 8);
        }
        if (c == 0 && tid < 64) {
            // Hk [64][4] fp32, parity buffer s&1. Safe via pipeline coupling
            // (any warp at tile s+2 chunk-0 implies all warps past tile s's
            // epilogue read of this buffer).
            cp16(sb + SM_HK + (uint32_t)(s & 1) * 1024 + tid * 16,
                 g_H + (kb + tid) * FOUT + fq * FB);
        }
        cp_async_mbar_arrive_noinc(mb_full + st * 8);
    };

    issue(0);
    issue(1);

    float acc[FB][4][2][4];            // 128 regs
    for (int s = 0; s < ntiles; s++) {
        const int t = cta + s * nsm;
        const int jbase = (t >> 9) * JT;
        const int kb0 = ((t >> 4) & 31) * KT;
        const int f0 = (t & 15) * FB;

#pragma unroll
        for (int f = 0; f < FB; f++)
#pragma unroll
            for (int mt = 0; mt < 4; mt++)
#pragma unroll
                for (int nt = 0; nt < 2; nt++)
#pragma unroll
                    for (int e = 0; e < 4; e++) acc[f][mt][nt][e] = 0.f;

        for (int c = 0; c < CPT; c++) {
            const int gc = s * CPT + c;
            const int st = gc & 3;
            // consumer waits completion of use u = gc>>2: parity u&1
            MBARRIER_WAIT_PARITY(mb_full + st * 8, (gc >> 2) & 1);

            const uint32_t abase = sb + (uint32_t)st * STAGE + ST_A;
            const uint32_t mbase = sb + (uint32_t)st * STAGE + ST_MH;
            const uint32_t hbase = sb + (uint32_t)st * STAGE + ST_H;

#pragma unroll
            for (int ks = 0; ks < 8; ks++) {
                // Producer call mid-compute: >=512 tensor cycles already
                // queued hide the cp16 burst + any empty-wait.
                if (ks == 2) issue(gc + 2);

                // B path first (longer chain: ldm -> HMUL2 -> mma)
                uint32_t bfr[4];
                ldm4(bfr, mbase + bn * 256 +
                              ((ks * 32 + bcol0) ^ ((bn & 7) * 16)));
                uint4 h0 = lds128(hbase + (ks * 8 + tg) * 16);
                uint4 h1 = lds128(hbase + (ks * 8 + tg + 4) * 16);

                uint32_t a[4][4];
#pragma unroll
                for (int mt = 0; mt < 4; mt++) {
                    int jr = jbw + mt * 16 + (lane & 15);
                    ldm4(a[mt], abase + jr * 256 +
                           ((((lane >> 4) * 16) + ks * 32) ^ ((jr & 7) * 16)));
                }
                const uint32_t* hp0 = (const uint32_t*)&h0;
                const uint32_t* hp1 = (const uint32_t*)&h1;
#pragma unroll
                for (int f = 0; f < FB; f++) {
                    uint32_t b00 = hmul2u(bfr[0], hp0[f]);
                    uint32_t b01 = hmul2u(bfr[1], hp1[f]);
                    uint32_t b10 = hmul2u(bfr[2], hp0[f]);
                    uint32_t b11 = hmul2u(bfr[3], hp1[f]);
#pragma unroll
                    for (int mt = 0; mt < 4; mt++) {
                        mma16816(acc[f][mt][0], a[mt], b00, b01);
                        mma16816(acc[f][mt][1], a[mt], b10, b11);
                    }
                }
            }
            // consumer done with stage st
            __syncwarp();
            if (lane == 0) MBARRIER_ARRIVE(mb_empty + st * 8);
        }

        // ---- epilogue (no block barrier): float2 mf LDG, Hk parity smem
        const float* Hks = (const float*)(smem + SM_HK + (size_t)(s & 1) * 1024);
#pragma unroll
        for (int mt = 0; mt < 4; mt++)
#pragma unroll
            for (int h2 = 0; h2 < 2; h2++) {
                const int j = jbw + mt * 16 + g + 8 * h2;
                float s4[FB] = {0.f, 0.f, 0.f, 0.f};
#pragma unroll
                for (int nt = 0; nt < 2; nt++) {
                    const int k0 = kbw + nt * 8 + tg * 2;
                    const float2 mp =
                        *(const float2*)&mf[(size_t)(jbase + j) * NN + kb0 + k0];
#pragma unroll
                    for (int e = 0; e < 2; e++) {
                        const float mv = e ? mp.y : mp.x;
                        const float4 hk = *(const float4*)&Hks[(k0 + e) * 4];
                        s4[0] += acc[0][mt][nt][h2 * 2 + e] * mv * hk.x;
                        s4[1] += acc[1][mt][nt][h2 * 2 + e] * mv * hk.y;
                        s4[2] += acc[2][mt][nt][h2 * 2 + e] * mv * hk.z;
                        s4[3] += acc[3][mt][nt][h2 * 2 + e] * mv * hk.w;
                    }
                }
#pragma unroll
                for (int f = 0; f < FB; f++) {
                    float v = s4[f];
                    v += __shfl_xor_sync(0xffffffffu, v, 1);
                    v += __shfl_xor_sync(0xffffffffu, v, 2);
                    if (tg == 0)
                        atomicAdd(&out[(size_t)(jbase + j) * FOUT + f0 + f], v);
                }
            }
    }
}

// ---------------- launch ----------------
extern "C" void kernel_launch(void* const* d_in, const int* in_sizes, int n_in,
                              void* d_out, int out_size) {
    const float* X  = (const float*)d_in[0];
    const float* A  = (const float*)d_in[1];
    const float* mf = (const float*)d_in[2];
    const float* mh = (const float*)d_in[3];
    const float* W  = (const float*)d_in[4];
    const float* b  = (const float*)d_in[5];
    float* out = (float*)d_out;

    int dev = 0, nsm = 148;
    cudaGetDevice(&dev);
    cudaDeviceGetAttribute(&nsm, cudaDevAttrMultiProcessorCount, dev);

    cudaFuncSetAttribute(interaction_main,
                         cudaFuncAttributeMaxDynamicSharedMemorySize, SMEM_TOTAL);

    prep_H<<<256, 512>>>(X, W, b, out);   // also zeroes out
    prep_A<<<4096, 512>>>(A);
    prep_mhT<<<dim3(64, 64), 256>>>(mh);
    interaction_main<<<nsm, 256, SMEM_TOTAL>>>(mf, out);
}